// round 2
// baseline (speedup 1.0000x reference)
#include <cuda_runtime.h>
#include <cstdint>

// Per-batch class-presence bitmasks (bits 0..5). Written fully by kernel A
// each call (deterministic, no reset needed), read by kernel B. B=64.
__device__ unsigned g_masks[64];

// ---------------------------------------------------------------------------
// Kernel A: one block per batch. OR-reduce int32 labels (0..5) into a 6-bit
// presence mask. Early exit: presence OR is monotone, so once the block's
// accumulated mask is 0x3F the rest of the batch cannot change the result.
// For uniform random labels this triggers after the first 4096-element chunk
// (16 KB), cutting traffic from 64 MiB to ~1 MiB. Worst case = full scan.
// ---------------------------------------------------------------------------
__global__ void presence_kernel(const int* __restrict__ target,
                                int n_vec4_per_batch /* int4 count = elems/4 */) {
    const int b = blockIdx.x;
    const int4* __restrict__ t4 =
        reinterpret_cast<const int4*>(target) + (long long)b * n_vec4_per_batch;

    __shared__ unsigned smask;
    if (threadIdx.x == 0) smask = 0u;
    __syncthreads();

    unsigned local = 0u;
    const int PER_ITER = 256 * 4;  // int4 per block per chunk (4096 labels)

    for (int base4 = 0; base4 < n_vec4_per_batch; base4 += PER_ITER) {
        #pragma unroll
        for (int k = 0; k < 4; k++) {
            int idx = base4 + threadIdx.x + k * 256;
            if (idx < n_vec4_per_batch) {
                int4 v = t4[idx];
                local |= (1u << (v.x & 31)) | (1u << (v.y & 31)) |
                         (1u << (v.z & 31)) | (1u << (v.w & 31));
            }
        }
        unsigned wm = __reduce_or_sync(0xffffffffu, local);
        if ((threadIdx.x & 31) == 0) atomicOr(&smask, wm);
        __syncthreads();
        if ((smask & 0x3Fu) == 0x3Fu) break;   // all 6 classes seen: done
        __syncthreads();
    }

    if (threadIdx.x == 0) g_masks[b] = smask;
}

// ---------------------------------------------------------------------------
// Kernel B: 384 threads, one per (batch, class) BCE term. Log terms clamped
// at -100 to match torch BCELoss / the jnp reference. Mean over 384 terms.
// ---------------------------------------------------------------------------
__global__ void loss_kernel(const float* __restrict__ se_pred,
                            float* __restrict__ out, int n_terms) {
    const int i = threadIdx.x;           // 0..383
    float v = 0.0f;
    if (i < n_terms) {
        const int b = i / 6;
        const int c = i - b * 6;
        const float p  = se_pred[i];
        const float t  = (float)((g_masks[b] >> c) & 1u);
        const float lp  = fmaxf(logf(p),    -100.0f);
        const float l1p = fmaxf(log1pf(-p), -100.0f);
        v = -(t * lp + (1.0f - t) * l1p);
    }

    // Block reduction: 12 warps -> shared -> first-warp reduce.
    __shared__ float sh[16];
    float w = v;
    #pragma unroll
    for (int o = 16; o > 0; o >>= 1) w += __shfl_down_sync(0xffffffffu, w, o);
    if ((i & 31) == 0) sh[i >> 5] = w;
    __syncthreads();
    if (i < 16) {
        float s = (i < 12) ? sh[i] : 0.0f;
        #pragma unroll
        for (int o = 8; o > 0; o >>= 1) s += __shfl_down_sync(0xffffu, s, o);
        if (i == 0) out[0] = s / (float)n_terms;
    }
}

// ---------------------------------------------------------------------------
extern "C" void kernel_launch(void* const* d_in, const int* in_sizes, int n_in,
                              void* d_out, int out_size) {
    // Resolve inputs by size: se_pred has 64*6 = 384 elements; target is huge.
    int se_idx = 0, tg_idx = 1;
    if (n_in >= 2 && in_sizes[0] > in_sizes[1]) { se_idx = 1; tg_idx = 0; }

    const float* se_pred = (const float*)d_in[se_idx];
    const int*   target  = (const int*)d_in[tg_idx];
    float* out = (float*)d_out;

    const int n_terms = in_sizes[se_idx];        // 384
    const int B = n_terms / 6;                   // 64
    const int per_batch = in_sizes[tg_idx] / B;  // 262144 int32 labels
    const int n_vec4 = per_batch / 4;            // int4 count per batch

    presence_kernel<<<B, 256>>>(target, n_vec4);
    loss_kernel<<<1, 384>>>(se_pred, out, n_terms);
}